// round 13
// baseline (speedup 1.0000x reference)
#include <cuda_runtime.h>
#include <cstdint>

// DiscreteAutoregressiveFlow: exact one-hot algebra over Z_257.
// next = (x_t * m[p] + c[p]) mod 257, per-state (m,c) from argmax of W[p]+b.
// Round 13: ONE mixed-role kernel, per-batch pipeline:
//   [33 table blocks][batch b: 16 extract | 16 zero | 16 chain blocks] x 64.
// Chain blocks wait (nanosleep spin) for their batch's extract blocks, so
// chain ALU overlaps the streaming of later batches. 27KB smem, regs<=42.

#define V        257
#define B        64
#define L        1024
#define SEGLEN   16
#define UNITS    4                        // segments per chain block
#define ROWS_PB  (UNITS * SEGLEN)         // 64 rows per chain block
#define BPB      16                       // chain blocks per batch
#define XPB      16                       // extract blocks per batch
#define ZPB      16                       // zero blocks per batch
#define GRPB     (XPB + ZPB + BPB)        // 48
#define TBLK     33                       // table blocks (264 warps >= 258)
#define WCHAIN   (B * BPB)                // 1024 chain blocks
#define REP      8                        // table replication factor
#define NST      258                      // states 0..256 plus 257 = ZERO
#define U4PB     ((L * V) / 4)            // 65792 uint4 per batch
#define SU4      (U4PB / 16)              // 4112 uint4 per streaming block
#define DEADE    (66048u << 9)            // dead: m=0, c=66048 -> slot 0

// Slot convention: slot 0 = ZERO/dead; slot s in [1,513] = state (s-1) mod 257.
// Step: z = x*m + c (alive z <= 65792); z mod 257 == (z&255)-(z>>8) (mod 257);
// w = lo - hi + 258 in [1,513] alive, 0 for the dead trap (hi=258). Branch-free.

__device__ unsigned g_tab[NST];                          // m | c<<9 (or DEADE)
__device__ __align__(16) int   g_xidx[B * L];
__device__ __align__(16) short g_bmap[B * BPB * NST];    // per-chain-block maps
__device__ int g_entry[B * BPB];
__device__ int g_tabdone;                                // all zero-init,
__device__ int g_xrdy[B];                                // self-resetting
__device__ int g_zrdy[B];
__device__ int g_done[B];
__device__ volatile int g_go[B];
__device__ int g_fin[B];
__device__ int g_allfin;

__device__ __forceinline__ int slot2state(int s) {       // [0,513] -> 0..257
    return (s == 0) ? V : ((s <= V) ? s - 1 : s - (V + 1));
}

__device__ __forceinline__ void markx(const uint4& v, int i4) {
    if (v.x | v.y | v.z | v.w) {
        unsigned a[4] = { v.x, v.y, v.z, v.w };
        int eb = i4 * 4;
        #pragma unroll
        for (int j = 0; j < 4; j++) {
            if (a[j] != 0u) {
                int idx = eb + j;
                int row = idx / V;                       // magic-mul div
                g_xidx[row] = idx - row * V;
            }
        }
    }
}

__global__ void __launch_bounds__(256, 6) k_F(const float* __restrict__ W,
                                              const float* __restrict__ bb,
                                              const int*   __restrict__ inv_table,
                                              const uint4* __restrict__ x4,
                                              uint4*       __restrict__ out4) {
    __shared__ unsigned tabR[514 * REP];                 // 16448 B
    __shared__ __align__(16) short segmapS[UNITS * NST]; // 2064 B
    __shared__ __align__(16) short bmapsS[BPB * NST];    // 8256 B
    __shared__ __align__(16) int   sxs[SEGLEN * UNITS];  // [t*4 + u]
    __shared__ int entryU[UNITS];
    __shared__ int isLast;

    int bid = blockIdx.x;
    int tid = threadIdx.x;

    // ---------------- role: per-state tables (first 33 blocks) --------------
    if (bid < TBLK) {
        int p    = bid * 8 + (tid >> 5);
        int lane = tid & 31;
        if (p < NST) {
            const float* wrow = (p < V) ? (W + (size_t)p * (2 * V)) : nullptr;
            int bestj[2];
            #pragma unroll
            for (int h = 0; h < 2; h++) {
                float bv = -3.402823466e38f;
                int   bj = 0;
                for (int j = lane; j < V; j += 32) {
                    int   col = h * V + j;
                    float v   = bb[col] + (wrow ? wrow[col] : 0.0f);
                    if (v > bv) { bv = v; bj = j; }      // first-max == jnp.argmax
                }
                #pragma unroll
                for (int off = 16; off; off >>= 1) {
                    float ov = __shfl_down_sync(0xffffffffu, bv, off);
                    int   oj = __shfl_down_sync(0xffffffffu, bj, off);
                    if (ov > bv || (ov == bv && oj < bj)) { bv = ov; bj = oj; }
                }
                bestj[h] = bj;
            }
            if (lane == 0) {
                int l = bestj[0], s = bestj[1];
                int m = inv_table[s];                    // 0 iff s==0
                unsigned e = DEADE;
                if (m != 0) {
                    int c = (V - (l * m) % V) % V;
                    e = (unsigned)m | ((unsigned)c << 9);
                }
                g_tab[p] = e;
            }
        }
        __threadfence();
        __syncthreads();
        if (tid == 0) atomicAdd(&g_tabdone, 1);
        return;
    }

    int g = bid - TBLK;
    int b = g / GRPB;
    int r = g - b * GRPB;

    // ---------------- role: extract (read stream) ----------------
    if (r < XPB) {
        int base = b * U4PB + r * SU4;                   // 4112 uint4
        #pragma unroll
        for (int half = 0; half < 2; half++) {
            int o = base + half * 2048 + tid;
            uint4 v[8];
            #pragma unroll
            for (int k = 0; k < 8; k++) v[k] = x4[o + k * 256];   // MLP 8
            #pragma unroll
            for (int k = 0; k < 8; k++) markx(v[k], o + k * 256);
        }
        if (tid < SU4 - 4096) {                          // 16 ragged
            int o = base + 4096 + tid;
            uint4 v = x4[o];
            markx(v, o);
        }
        __threadfence();
        __syncthreads();
        if (tid == 0) atomicAdd(&g_xrdy[b], 1);
        return;
    }

    // ---------------- role: zero-fill (write stream) ----------------
    if (r < XPB + ZPB) {
        int base = b * U4PB + (r - XPB) * SU4;           // 4112 uint4
        uint4 z = make_uint4(0u, 0u, 0u, 0u);
        #pragma unroll
        for (int k = 0; k < 16; k++) out4[base + tid + k * 256] = z;
        if (tid < SU4 - 4096) out4[base + 4096 + tid] = z;
        __threadfence();
        __syncthreads();
        if (tid == 0) atomicAdd(&g_zrdy[b], 1);
        return;
    }

    // ---------------- role: chain block ----------------
    int blk = r - XPB - ZPB;                             // 0..15
    int rowbase = b * L + blk * ROWS_PB;

    if (tid == 0) {
        while (*(volatile int*)&g_tabdone < TBLK) __nanosleep(32);
        while (*(volatile int*)&g_xrdy[b] < XPB) __nanosleep(32);
    }
    __syncthreads();
    __threadfence();                                     // acquire producers

    for (int i = tid; i < 514 * REP; i += 256)
        tabR[i] = g_tab[slot2state(i >> 3)];             // REP = 8
    if (tid < ROWS_PB) {
        int u = tid >> 4, t = tid & 15;
        sxs[t * 4 + u] = g_xidx[rowbase + u * SEGLEN + t];
    }
    __syncthreads();

    // ---- segment maps: 4 chains/thread + extras (states 256/257, t<8) ----
    int rep = tid & (REP - 1);
    int xst = 256 + (tid & 1);
    int xun = (tid >> 1) & 3;
    bool extra = (tid < 8);

    int slot[5];
    #pragma unroll
    for (int j = 0; j < 4; j++) slot[j] = tid + 1;       // state tid -> slot tid+1
    slot[4] = (xst == V) ? 0 : xst + 1;

    #pragma unroll
    for (int t = 0; t < SEGLEN; t++) {
        uint4 xv = *(const uint4*)&sxs[t * 4];           // broadcast LDS.128
        unsigned xs[4] = { xv.x, xv.y, xv.z, xv.w };
        #pragma unroll
        for (int j = 0; j < 4; j++) {
            unsigned e = tabR[slot[j] * REP + rep];
            unsigned z = xs[j] * (e & 511u) + (e >> 9);
            slot[j] = (int)(z & 255u) - (int)(z >> 8) + 258;
        }
        if (extra) {
            unsigned e = tabR[slot[4] * REP + rep];
            unsigned z = (unsigned)sxs[t * 4 + xun] * (e & 511u) + (e >> 9);
            slot[4] = (int)(z & 255u) - (int)(z >> 8) + 258;
        }
    }

    #pragma unroll
    for (int j = 0; j < 4; j++)
        segmapS[j * NST + tid] = (short)slot2state(slot[j]);
    if (extra)
        segmapS[xun * NST + xst] = (short)slot2state(slot[4]);
    __syncthreads();

    // ---- compose own 4 segmaps -> block-map, publish ----
    {
        int gi = b * BPB + blk;
        int cur = segmapS[tid];
        #pragma unroll
        for (int u = 1; u < UNITS; u++) cur = segmapS[u * NST + cur];
        g_bmap[(size_t)gi * NST + tid] = (short)cur;
        if (tid < 2) {
            int c2 = segmapS[256 + tid];
            #pragma unroll
            for (int u = 1; u < UNITS; u++) c2 = segmapS[u * NST + c2];
            g_bmap[(size_t)gi * NST + 256 + tid] = (short)c2;
        }
    }
    __threadfence();
    __syncthreads();
    if (tid == 0) isLast = (atomicAdd(&g_done[b], 1) == BPB - 1);
    __syncthreads();

    // ---- last chain block of batch: stitch 16 block-maps in SMEM ----
    if (isLast) {
        __threadfence();
        const uint4* src = (const uint4*)(g_bmap + (size_t)(b * BPB) * NST);
        uint4* dst = (uint4*)bmapsS;
        dst[tid]       = src[tid];                       // 516 uint4 total
        dst[256 + tid] = src[256 + tid];
        if (tid < 4) dst[512 + tid] = src[512 + tid];
        __syncthreads();
        if (tid == 0) {
            int st = V;  // ZERO
            #pragma unroll
            for (int k = 0; k < BPB; k++) {
                g_entry[b * BPB + k] = st;
                st = bmapsS[k * NST + st];
            }
            __threadfence();
            g_go[b] = 1;                                 // release
        }
    }

    // ---- wait for stitch + zeros, then replay + scatter ----
    if (tid == 0) {
        while (g_go[b] == 0) __nanosleep(32);
        while (*(volatile int*)&g_zrdy[b] < ZPB) __nanosleep(32);
    }
    __syncthreads();
    __threadfence();

    if (tid == 0) {
        int st = g_entry[b * BPB + blk];
        #pragma unroll
        for (int u = 0; u < UNITS; u++) {
            entryU[u] = st;
            st = segmapS[u * NST + st];
        }
    }
    __syncthreads();

    {
        int w = tid >> 5, lane = tid & 31;
        if (w < UNITS && lane == 0) {
            int ent = entryU[w];
            int sl  = (ent == V) ? 0 : ent + 1;
            float* orow = (float*)out4 + (size_t)(rowbase + w * SEGLEN) * V;
            #pragma unroll
            for (int t = 0; t < SEGLEN; t++) {
                unsigned e = tabR[sl * REP];
                unsigned z = (unsigned)sxs[t * 4 + w] * (e & 511u) + (e >> 9);
                sl = (int)(z & 255u) - (int)(z >> 8) + 258;
                if (sl != 0) {
                    int oi = (sl <= V) ? sl - 1 : sl - (V + 1);
                    orow[(size_t)t * V + oi] = 1.0f;
                }
            }
        }
    }
    __syncthreads();

    if (tid == 0) {                                      // self-reset for replay
        if (atomicAdd(&g_fin[b], 1) == BPB - 1) {
            g_done[b] = 0;
            g_fin[b]  = 0;
            g_go[b]   = 0;
            g_xrdy[b] = 0;
            g_zrdy[b] = 0;
        }
        if (atomicAdd(&g_allfin, 1) == WCHAIN - 1) {
            g_tabdone = 0;
            g_allfin  = 0;
        }
    }
}

// ---------------------------------------------------------------------------
extern "C" void kernel_launch(void* const* d_in, const int* in_sizes, int n_in,
                              void* d_out, int out_size) {
    const float* x   = (const float*)d_in[0];   // [B, L, V] f32
    const float* W   = (const float*)d_in[1];   // [V, 2V]   f32
    const float* bb  = (const float*)d_in[2];   // [2V]      f32
    const int*   inv = (const int*)  d_in[3];   // [V]       i32

    k_F<<<TBLK + B * GRPB, 256>>>(W, bb, inv, (const uint4*)x, (uint4*)d_out);
}

// round 14
// speedup vs baseline: 1.3559x; 1.3559x over previous
#include <cuda_runtime.h>
#include <cstdint>

// DiscreteAutoregressiveFlow: exact one-hot algebra over Z_257.
// next = (x_t * m[p] + c[p]) mod 257, per-state (m,c) from argmax of W[p]+b.
// Round 14: two kernels (r10 skeleton). k_A additionally writes the doubled,
// x16-replicated table to GMEM (g_tabRD) so k_BC's fill is 8xLDG.128. k_BC:
// 512 blocks / ONE wave (42KB smem), 8 chains/thread, hierarchical stitch
// (block-maps + serial L2 gathers) and 64-thread replay in the last block.

#define V        257
#define B        64
#define L        1024
#define SEGLEN   16
#define UNITS    8                        // segments per chain block
#define BPB      8                        // chain blocks per batch
#define SEGBLK   (B * BPB)                // 512
#define REP      16                       // table replication factor
#define NST      258                      // states 0..256 plus 257 = ZERO
#define NSLOT    514                      // doubled-table slots
#define TABW     (NSLOT * REP)            // 8224 words
#define TOTAL4   ((B * L * V) / 4)        // 4,214,784 uint4
#define TBLK     33                       // table blocks (264 warps >= 258)
#define MIXB     (TOTAL4 / 2048)          // 2058 blocks per stream role
#define DEADE    (66048u << 9)            // dead: m=0, c=66048 -> slot 0

// Slot convention: slot 0 = state 257 (ZERO); slot s in [1,513] = state
// (s-1) mod 257. Step: z = x*m + c (alive z <= 65792); z mod 257 ==
// (z&255)-(z>>8) (mod 257); w = lo-hi+258 in [1,513] alive, 0 for the dead
// trap (m=0, c=66048 -> hi=258). Branch-free; dead -> ZERO state, no output.

__device__ __align__(16) unsigned g_tabRD[TABW];         // doubled + replicated
__device__ __align__(16) int   g_xidx[B * L];
__device__ __align__(16) short g_bmap[SEGBLK * NST];     // composed block maps
__device__ __align__(16) short g_seg[SEGBLK * UNITS * NST];  // per-unit maps
__device__ int g_done[B];                                // zero-init; self-reset

// ---------------------------------------------------------------------------
// K_A: tables (33 blocks) + extract (read stream) + zero-fill (write stream).
// Table warps ALSO write the replicated doubled table to g_tabRD.
// ---------------------------------------------------------------------------
__global__ void __launch_bounds__(256) k_A(const float* __restrict__ W,
                                           const float* __restrict__ bb,
                                           const int*   __restrict__ inv_table,
                                           const uint4* __restrict__ x,
                                           uint4*       __restrict__ out) {
    int bid = blockIdx.x;
    int tid = threadIdx.x;

    if (bid < TBLK) {
        int p    = bid * 8 + (tid >> 5);
        int lane = tid & 31;
        if (p >= NST) return;
        const float* wrow = (p < V) ? (W + (size_t)p * (2 * V)) : nullptr;
        int bestj[2];
        #pragma unroll
        for (int h = 0; h < 2; h++) {
            float bv = -3.402823466e38f;
            int   bj = 0;
            for (int j = lane; j < V; j += 32) {
                int   col = h * V + j;
                float v   = bb[col] + (wrow ? wrow[col] : 0.0f);
                if (v > bv) { bv = v; bj = j; }     // first-max == jnp.argmax
            }
            #pragma unroll
            for (int off = 16; off; off >>= 1) {
                float ov = __shfl_down_sync(0xffffffffu, bv, off);
                int   oj = __shfl_down_sync(0xffffffffu, bj, off);
                if (ov > bv || (ov == bv && oj < bj)) { bv = ov; bj = oj; }
            }
            bestj[h] = bj;
        }
        unsigned e = 0u;
        if (lane == 0) {
            int l = bestj[0], s = bestj[1];
            int m = inv_table[s];                 // 0 iff s==0
            e = DEADE;
            if (m != 0) {
                int c = (V - (l * m) % V) % V;    // (-l*m) mod V
                e = (unsigned)m | ((unsigned)c << 9);
            }
        }
        e = __shfl_sync(0xffffffffu, e, 0);
        // replicate into the doubled table: state p -> slots
        //   p<=255: p+1 and p+258;  p==256: 257 only;  p==257 (ZERO): 0 only.
        int slotA = (p == V) ? 0 : p + 1;
        if (lane < REP) g_tabRD[slotA * REP + lane] = e;
        else if (p < 256) g_tabRD[(p + 258) * REP + (lane - REP)] = e;
        return;
    }

    int mm   = bid - TBLK;
    int unit = mm >> 1;
    int base = unit * 2048 + tid;

    if (mm & 1) {
        uint4 z = make_uint4(0u, 0u, 0u, 0u);
        #pragma unroll
        for (int k = 0; k < 8; k++) out[base + k * 256] = z;
        return;
    }

    // extract: 8 coalesced uint4 loads front-batched (MLP_p1 = 8)
    uint4 v[8];
    #pragma unroll
    for (int k = 0; k < 8; k++) v[k] = x[base + k * 256];
    #pragma unroll
    for (int k = 0; k < 8; k++) {
        if (v[k].x | v[k].y | v[k].z | v[k].w) {
            unsigned a[4] = { v[k].x, v[k].y, v[k].z, v[k].w };
            int eb = (base + k * 256) * 4;
            #pragma unroll
            for (int j = 0; j < 4; j++) {
                if (a[j] != 0u) {
                    int idx = eb + j;
                    int row = idx / V;
                    g_xidx[row] = idx - row * V;
                }
            }
        }
    }
}

// ---------------------------------------------------------------------------
// K_BC: 512 blocks, one wave. Per block: fill tabR (coalesced), run 8 chains
// per thread (+16 extra for states 256/257), compose -> block map, publish.
// Last block per batch: hierarchical stitch (8+8 serial L2 gathers) + replay
// (64 threads x 16 steps) + scatter into the pre-zeroed output.
// ---------------------------------------------------------------------------
__global__ void __launch_bounds__(256) k_BC(float* __restrict__ out) {
    __shared__ __align__(16) unsigned tabR[TABW];        // 32896 B
    __shared__ __align__(16) short segmapS[UNITS * NST]; // 4128 B
    __shared__ __align__(16) int   sx[L];                // 4096 B
    __shared__ __align__(16) int   sxs[SEGLEN * UNITS];  // [t*8 + u]
    __shared__ short entryS[UNITS * BPB];                // 64 segment entries
    __shared__ short blkentS[BPB];
    __shared__ int   isLast;

    int bid = blockIdx.x;
    int tid = threadIdx.x;
    int b   = bid / BPB;
    int blk = bid % BPB;

    // fill: 2056 uint4, fully coalesced
    {
        const uint4* src = (const uint4*)g_tabRD;
        uint4* dst = (uint4*)tabR;
        #pragma unroll
        for (int k = 0; k < 8; k++) dst[tid + k * 256] = src[tid + k * 256];
        if (tid < (TABW / 4) - 2048) dst[2048 + tid] = src[2048 + tid];
    }
    if (tid < UNITS * SEGLEN) {
        int u = tid >> 4, t = tid & 15;                  // coalesced LDG per unit
        sxs[t * 8 + u] = g_xidx[b * L + (blk * UNITS + u) * SEGLEN + t];
    }
    __syncthreads();

    // ---- segment maps: 8 branch-free chains/thread + extra on t<16 ----
    int rep = tid & (REP - 1);
    int xst = 256 + (tid & 1);          // extra-chain state (threads 0..15)
    int xun = (tid >> 1) & 7;           // extra-chain unit
    bool extra = (tid < 16);

    int slot[9];
    #pragma unroll
    for (int j = 0; j < 8; j++) slot[j] = tid + 1;       // state tid -> slot tid+1
    slot[8] = (xst == V) ? 0 : xst + 1;

    #pragma unroll
    for (int t = 0; t < SEGLEN; t++) {
        uint4 xv0 = *(const uint4*)&sxs[t * 8];
        uint4 xv1 = *(const uint4*)&sxs[t * 8 + 4];
        unsigned xs[8] = { xv0.x, xv0.y, xv0.z, xv0.w,
                           xv1.x, xv1.y, xv1.z, xv1.w };
        #pragma unroll
        for (int j = 0; j < 8; j++) {
            unsigned e = tabR[slot[j] * REP + rep];
            unsigned z = xs[j] * (e & 511u) + (e >> 9);
            slot[j] = (int)(z & 255u) - (int)(z >> 8) + 258;
        }
        if (extra) {
            unsigned e = tabR[slot[8] * REP + rep];
            unsigned z = (unsigned)sxs[t * 8 + xun] * (e & 511u) + (e >> 9);
            slot[8] = (int)(z & 255u) - (int)(z >> 8) + 258;
        }
    }

    #pragma unroll
    for (int j = 0; j < 8; j++) {
        int s = slot[j];
        segmapS[j * NST + tid] =
            (short)((s == 0) ? V : ((s <= V) ? s - 1 : s - (V + 1)));
    }
    if (extra) {
        int s = slot[8];
        segmapS[xun * NST + xst] =
            (short)((s == 0) ? V : ((s <= V) ? s - 1 : s - (V + 1)));
    }
    __syncthreads();

    // ---- publish per-unit maps (coalesced uint4) + composed block map ----
    {
        const uint4* src = (const uint4*)segmapS;        // 258 uint4
        uint4* dst = (uint4*)(g_seg + (size_t)bid * UNITS * NST);
        dst[tid] = src[tid];
        if (tid < 2) dst[256 + tid] = src[256 + tid];
    }
    for (int p = tid; p < NST; p += 256) {
        int cur = segmapS[p];
        #pragma unroll
        for (int u = 1; u < UNITS; u++) cur = segmapS[u * NST + cur];
        g_bmap[(size_t)bid * NST + p] = (short)cur;
    }
    __threadfence();
    __syncthreads();
    if (tid == 0) isLast = (atomicAdd(&g_done[b], 1) == BPB - 1);
    __syncthreads();
    if (!isLast) return;
    __threadfence();                                     // acquire peers' maps

    // ---- hierarchical stitch ----
    ((uint4*)sx)[tid] = ((const uint4*)(g_xidx + b * L))[tid];  // batch x
    if (tid == 0) {
        int st = V;                                      // ZERO
        #pragma unroll
        for (int k = 0; k < BPB; k++) {
            blkentS[k] = (short)st;
            st = g_bmap[(size_t)(b * BPB + k) * NST + st];   // 8 serial L2
        }
        g_done[b] = 0;                                   // self-reset for replay
    }
    __syncthreads();
    if (tid < BPB) {
        int k = tid;
        int e = blkentS[k];
        const short* seg = g_seg + (size_t)(b * BPB + k) * UNITS * NST;
        #pragma unroll
        for (int u = 0; u < UNITS; u++) {
            entryS[k * UNITS + u] = (short)e;
            e = seg[u * NST + e];                        // 8 serial L2
        }
    }
    __syncthreads();

    // ---- replay + scatter: 64 threads, one 16-step chain each ----
    if (tid < BPB * UNITS) {
        int seg = tid;                                   // global segment in batch
        int ent = entryS[seg];
        int sl  = (ent == V) ? 0 : ent + 1;
        float* orow = out + (size_t)(b * L + seg * SEGLEN) * V;
        #pragma unroll
        for (int t = 0; t < SEGLEN; t++) {
            unsigned e = tabR[sl * REP + (tid & (REP - 1))];
            unsigned z = (unsigned)sx[seg * SEGLEN + t] * (e & 511u) + (e >> 9);
            sl = (int)(z & 255u) - (int)(z >> 8) + 258;
            if (sl != 0) {
                int oi = (sl <= V) ? sl - 1 : sl - (V + 1);
                orow[(size_t)t * V + oi] = 1.0f;
            }
        }
    }
}

// ---------------------------------------------------------------------------
extern "C" void kernel_launch(void* const* d_in, const int* in_sizes, int n_in,
                              void* d_out, int out_size) {
    const float* x   = (const float*)d_in[0];   // [B, L, V] f32
    const float* W   = (const float*)d_in[1];   // [V, 2V]   f32
    const float* bb  = (const float*)d_in[2];   // [2V]      f32
    const int*   inv = (const int*)  d_in[3];   // [V]       i32

    k_A<<<TBLK + 2 * MIXB, 256>>>(W, bb, inv, (const uint4*)x, (uint4*)d_out);
    k_BC<<<SEGBLK, 256>>>((float*)d_out);
}